// round 9
// baseline (speedup 1.0000x reference)
#include <cuda_runtime.h>
#include <cuda_fp16.h>
#include <cstdint>

// =============================================================================
// SVDLinearAddition, single-product fp16 on mma.sync (tensor pipe):
//   prep:  xh = fp16(x); uh = fp16(U*(S+eps)); vh = fp16(Vt^T)
//   GEMM1: w = uh @ vh^T          -> fp16 epilogue (wh)
//   GEMM2: y = xh @ wh^T + bias   -> fp32 epilogue
// 128x128 CTA tile, warp 64x32, KC=64, 3-stage cp.async, 2 CTAs/SM.
// R9: XOR-swizzle address precompute + affine cp.async addressing to cut
//     fma/alu-pipe overhead (measured 20% of issue slots in R8).
// =============================================================================

__device__ uint16_t g_xh[8192ull * 4096];
__device__ uint16_t g_uh[4096ull * 4096];
__device__ uint16_t g_vh[4096ull * 4096];
__device__ uint16_t g_wh[4096ull * 4096];

// ---------------------------- helpers ---------------------------------------
static __device__ __forceinline__ uint32_t smem_u32(const void* p) {
    uint32_t a;
    asm("{ .reg .u64 t; cvta.to.shared.u64 t, %1; cvt.u32.u64 %0, t; }"
        : "=r"(a) : "l"(p));
    return a;
}
static __device__ __forceinline__ uint32_t sw128(uint32_t o) {
    return o ^ ((o >> 3) & 0x70);
}
static __device__ __forceinline__ void ldsm4(uint32_t& r0, uint32_t& r1,
                                             uint32_t& r2, uint32_t& r3, uint32_t a) {
    asm volatile("ldmatrix.sync.aligned.m8n8.x4.shared.b16 {%0,%1,%2,%3}, [%4];"
                 : "=r"(r0), "=r"(r1), "=r"(r2), "=r"(r3) : "r"(a));
}
static __device__ __forceinline__ void mma16816(float& c0, float& c1, float& c2, float& c3,
                                                uint32_t a0, uint32_t a1, uint32_t a2, uint32_t a3,
                                                uint32_t b0, uint32_t b1) {
    asm volatile(
        "mma.sync.aligned.m16n8k16.row.col.f32.f16.f16.f32 "
        "{%0,%1,%2,%3}, {%4,%5,%6,%7}, {%8,%9}, {%0,%1,%2,%3};"
        : "+f"(c0), "+f"(c1), "+f"(c2), "+f"(c3)
        : "r"(a0), "r"(a1), "r"(a2), "r"(a3), "r"(b0), "r"(b1));
}
static __device__ __forceinline__ void cpa16(uint32_t s, const void* g) {
    asm volatile("cp.async.cg.shared.global [%0], [%1], 16;" :: "r"(s), "l"(g));
}
static __device__ __forceinline__ void cpa_commit() {
    asm volatile("cp.async.commit_group;");
}

// ------------------------------ prep kernels --------------------------------
__global__ void prep_half(const float* __restrict__ src,
                          uint16_t* __restrict__ hi, size_t n4)
{
    uint2* h2 = reinterpret_cast<uint2*>(hi);
    for (size_t i = blockIdx.x * blockDim.x + threadIdx.x; i < n4;
         i += (size_t)gridDim.x * blockDim.x) {
        float4 v = reinterpret_cast<const float4*>(src)[i];
        __half2 h01 = __floats2half2_rn(v.x, v.y);
        __half2 h23 = __floats2half2_rn(v.z, v.w);
        uint2 hu;
        hu.x = *reinterpret_cast<uint32_t*>(&h01);
        hu.y = *reinterpret_cast<uint32_t*>(&h23);
        h2[i] = hu;
    }
}
__global__ void prep_scale_half(const float* __restrict__ U,
                                const float* __restrict__ S,
                                const float* __restrict__ eps,
                                uint16_t* __restrict__ hi, size_t n4, int rq)
{
    uint2* h2 = reinterpret_cast<uint2*>(hi);
    for (size_t i = blockIdx.x * blockDim.x + threadIdx.x; i < n4;
         i += (size_t)gridDim.x * blockDim.x) {
        size_t c4 = i % rq;
        float4 v = reinterpret_cast<const float4*>(U)[i];
        float4 sv = reinterpret_cast<const float4*>(S)[c4];
        float4 ev = reinterpret_cast<const float4*>(eps)[c4];
        v.x *= (sv.x + ev.x); v.y *= (sv.y + ev.y);
        v.z *= (sv.z + ev.z); v.w *= (sv.w + ev.w);
        __half2 h01 = __floats2half2_rn(v.x, v.y);
        __half2 h23 = __floats2half2_rn(v.z, v.w);
        uint2 hu;
        hu.x = *reinterpret_cast<uint32_t*>(&h01);
        hu.y = *reinterpret_cast<uint32_t*>(&h23);
        h2[i] = hu;
    }
}
// Vt [r][dIn] -> vh fp16 [dIn][r] (transpose)
__global__ void prep_transpose_half(const float* __restrict__ Vt,
                                    uint16_t* __restrict__ hi, int R, int dIn)
{
    __shared__ float tile[32][33];
    const int tx = threadIdx.x, ty = threadIdx.y;  // 32 x 8
    const int k0 = blockIdx.y * 32, n0 = blockIdx.x * 32;
    #pragma unroll
    for (int j = 0; j < 4; j++)
        tile[ty + j * 8][tx] = Vt[(size_t)(k0 + ty + j * 8) * dIn + n0 + tx];
    __syncthreads();
    #pragma unroll
    for (int j = 0; j < 4; j++) {
        float v = tile[tx][ty + j * 8];
        __half h = __float2half_rn(v);
        hi[(size_t)(n0 + ty + j * 8) * R + k0 + tx] = *reinterpret_cast<uint16_t*>(&h);
    }
}

// ------------------------------ GEMM core -----------------------------------
// CTA tile 128(m) x 128(n), KC=64 (128B rows, SW128). 8 warps (2m x 4n), 64x32.
// stage: A 16K | B 16K = 32KB; 3 stages = 96KB. 2 CTAs/SM.
#define KC 64
#define T_B 16384
#define STAGE 32768
#define NSTAGE 3
#define SMEM_BYTES (NSTAGE * STAGE)

template<int EPI>   // 0: fp16 output (GEMM1), 1: fp32 + bias (GEMM2)
__global__ __launch_bounds__(256, 2)
void gemm_f16(const uint16_t* __restrict__ Agh,
              const uint16_t* __restrict__ Bgh,
              float* __restrict__ Yout, const float* __restrict__ bias,
              uint16_t* __restrict__ Wh,
              int M, int N, int K)
{
    extern __shared__ char smem[];
    const uint32_t sb = smem_u32(smem);

    const int tid = threadIdx.x;
    const int wid = tid >> 5, lane = tid & 31;
    const int m0 = blockIdx.y * 128;
    const int n0 = blockIdx.x * 128;
    const int mw = (wid & 1) * 64;
    const int nw = (wid >> 1) * 32;

    // --- precomputed swizzled ldsm addresses (kk applied via XOR of bits 5-6)
    const uint32_t rowA = mw + (lane & 7) + ((lane >> 3) & 1) * 8;
    const uint32_t colA = ((lane >> 4) & 1) * 16;
    const uint32_t rowB = nw + (lane & 7) + ((lane >> 4) & 1) * 8;
    const uint32_t colB = ((lane >> 3) & 1) * 16;
    uint32_t aAddr[4], bAddr[2];
    #pragma unroll
    for (int mi = 0; mi < 4; mi++) aAddr[mi] = sw128((rowA + mi * 16) * 128 + colA);
    #pragma unroll
    for (int p = 0; p < 2; p++)  bAddr[p]  = sw128((rowB + p * 16) * 128 + colB) + T_B;

    float acc[4][4][4];
    #pragma unroll
    for (int i = 0; i < 4; i++)
        #pragma unroll
        for (int j = 0; j < 4; j++)
            #pragma unroll
            for (int q = 0; q < 4; q++) acc[i][j][q] = 0.f;

    const int KI = K / KC;

    // --- affine cp.async addressing: base ptr/offset + constant strides
    const int ldRow = tid >> 3;          // 0..31 (i adds +32)
    const int ldQ   = tid & 7;
    const uint32_t smBase = sw128((uint32_t)(ldRow * 128 + ldQ * 16));   // +4096/i
    const uint16_t* pA = Agh + (size_t)(m0 + ldRow) * K + ldQ * 8;       // +32K/i
    const uint16_t* pB = Bgh + (size_t)(n0 + ldRow) * K + ldQ * 8;

    auto ISSUE = [&](int slot, int kt) {
        const uint32_t base = sb + (uint32_t)slot * STAGE + smBase;
        const size_t kof = (size_t)kt * KC;
        #pragma unroll
        for (int i = 0; i < 4; i++)
            cpa16(base + i * 4096, pA + kof + (size_t)i * 32 * K);
        #pragma unroll
        for (int i = 0; i < 4; i++)
            cpa16(base + T_B + i * 4096, pB + kof + (size_t)i * 32 * K);
        cpa_commit();
    };

    ISSUE(0, 0);
    ISSUE(1, 1);

    for (int kt = 0; kt < KI; kt++) {
        asm volatile("cp.async.wait_group %0;" :: "n"(NSTAGE - 2) : "memory");
        __syncthreads();
        if (kt + NSTAGE - 1 < KI)
            ISSUE((kt + NSTAGE - 1) % NSTAGE, kt + NSTAGE - 1);

        const uint32_t stg = sb + (uint32_t)(kt % NSTAGE) * STAGE;

        #pragma unroll
        for (int kk = 0; kk < 4; kk++) {
            const uint32_t kko = (uint32_t)kk << 5;
            uint32_t ah[4][4], bh[2][4];
            #pragma unroll
            for (int mi = 0; mi < 4; mi++)
                ldsm4(ah[mi][0], ah[mi][1], ah[mi][2], ah[mi][3],
                      stg + (aAddr[mi] ^ kko));
            #pragma unroll
            for (int p = 0; p < 2; p++)
                ldsm4(bh[p][0], bh[p][1], bh[p][2], bh[p][3],
                      stg + (bAddr[p] ^ kko));
            #pragma unroll
            for (int mi = 0; mi < 4; mi++) {
                #pragma unroll
                for (int ni = 0; ni < 4; ni++) {
                    float* c = acc[mi][ni];
                    mma16816(c[0], c[1], c[2], c[3],
                             ah[mi][0], ah[mi][1], ah[mi][2], ah[mi][3],
                             bh[ni >> 1][(ni & 1) * 2], bh[ni >> 1][(ni & 1) * 2 + 1]);
                }
            }
        }
    }

    // ------------------------------ epilogue ---------------------------------
    const int erow = lane >> 2;
    const int ecol = (lane & 3) * 2;
    if (EPI == 1) {
        #pragma unroll
        for (int ni = 0; ni < 4; ni++) {
            int n = n0 + nw + ni * 8 + ecol;
            float2 bv = *reinterpret_cast<const float2*>(bias + n);
            #pragma unroll
            for (int mi = 0; mi < 4; mi++) {
                int m = m0 + mw + mi * 16 + erow;
                float* c = acc[mi][ni];
                *reinterpret_cast<float2*>(Yout + (size_t)m * N + n) =
                    make_float2(c[0] + bv.x, c[1] + bv.y);
                *reinterpret_cast<float2*>(Yout + (size_t)(m + 8) * N + n) =
                    make_float2(c[2] + bv.x, c[3] + bv.y);
            }
        }
    } else {
        #pragma unroll
        for (int ni = 0; ni < 4; ni++) {
            int n = n0 + nw + ni * 8 + ecol;
            #pragma unroll
            for (int mi = 0; mi < 4; mi++) {
                int m = m0 + mw + mi * 16 + erow;
                float* c = acc[mi][ni];
                #pragma unroll
                for (int half = 0; half < 2; half++) {
                    __half2 h = __floats2half2_rn(c[half * 2], c[half * 2 + 1]);
                    *reinterpret_cast<uint32_t*>(Wh + (size_t)(m + half * 8) * N + n) =
                        *reinterpret_cast<uint32_t*>(&h);
                }
            }
        }
    }
}

// =============================================================================
// Entry. Inputs: x, U, S, Vt, epsilon, bias
// =============================================================================
extern "C" void kernel_launch(void* const* d_in, const int* in_sizes, int n_in,
                              void* d_out, int out_size)
{
    const float* x    = (const float*)d_in[0];
    const float* U    = (const float*)d_in[1];
    const float* S    = (const float*)d_in[2];
    const float* Vt   = (const float*)d_in[3];
    const float* eps  = (const float*)d_in[4];
    const float* bias = (const float*)d_in[5];
    float* y = (float*)d_out;

    const int r    = in_sizes[2];          // 4096
    const int dIn  = in_sizes[3] / r;      // 4096
    const int dOut = in_sizes[1] / r;      // 4096
    const int M    = in_sizes[0] / dIn;    // 8192

    cudaFuncSetAttribute(gemm_f16<0>, cudaFuncAttributeMaxDynamicSharedMemorySize, SMEM_BYTES);
    cudaFuncSetAttribute(gemm_f16<1>, cudaFuncAttributeMaxDynamicSharedMemorySize, SMEM_BYTES);

    uint16_t *xh, *uh, *vh, *wh;
    cudaGetSymbolAddress((void**)&xh, g_xh);
    cudaGetSymbolAddress((void**)&uh, g_uh);
    cudaGetSymbolAddress((void**)&vh, g_vh);
    cudaGetSymbolAddress((void**)&wh, g_wh);

    prep_half<<<4096, 256>>>(x, xh, (size_t)M * dIn / 4);
    prep_scale_half<<<4096, 256>>>(U, S, eps, uh, (size_t)dOut * r / 4, r / 4);
    {
        dim3 grid(dIn / 32, r / 32), blk(32, 8);
        prep_transpose_half<<<grid, blk>>>(Vt, vh, r, dIn);
    }
    // GEMM1: w[dOut, dIn] = uh @ vh^T (fp16 output)
    {
        dim3 grid(dIn / 128, dOut / 128);
        gemm_f16<0><<<grid, 256, SMEM_BYTES>>>(uh, vh, nullptr, nullptr, wh,
                                               dOut, dIn, r);
    }
    // GEMM2: y[M, dOut] = xh @ wh^T + bias
    {
        dim3 grid(dOut / 128, M / 128);
        gemm_f16<1><<<grid, 256, SMEM_BYTES>>>(xh, wh, y, bias, nullptr,
                                               M, dOut, dIn);
    }
}

// round 10
// speedup vs baseline: 1.0423x; 1.0423x over previous
#include <cuda_runtime.h>
#include <cuda_fp16.h>
#include <cstdint>

// =============================================================================
// SVDLinearAddition, single-product fp16 on mma.sync (tensor pipe):
//   prep:  xh = fp16(x); uh = fp16(U*(S+eps)); vh = fp16(Vt^T)
//   GEMM1: w = uh @ vh^T          -> fp16 epilogue (wh)
//   GEMM2: y = xh @ wh^T + bias   -> fp32 epilogue
// 128x128 CTA tile, warp 64x32, KC=64, 3-stage cp.async, 2 CTAs/SM.
// R10: fragment double-buffering across kk steps (break ldsm->mma RAW chain).
// =============================================================================

__device__ uint16_t g_xh[8192ull * 4096];
__device__ uint16_t g_uh[4096ull * 4096];
__device__ uint16_t g_vh[4096ull * 4096];
__device__ uint16_t g_wh[4096ull * 4096];

// ---------------------------- helpers ---------------------------------------
static __device__ __forceinline__ uint32_t smem_u32(const void* p) {
    uint32_t a;
    asm("{ .reg .u64 t; cvta.to.shared.u64 t, %1; cvt.u32.u64 %0, t; }"
        : "=r"(a) : "l"(p));
    return a;
}
static __device__ __forceinline__ uint32_t sw128(uint32_t o) {
    return o ^ ((o >> 3) & 0x70);
}
static __device__ __forceinline__ void ldsm4(uint32_t& r0, uint32_t& r1,
                                             uint32_t& r2, uint32_t& r3, uint32_t a) {
    asm volatile("ldmatrix.sync.aligned.m8n8.x4.shared.b16 {%0,%1,%2,%3}, [%4];"
                 : "=r"(r0), "=r"(r1), "=r"(r2), "=r"(r3) : "r"(a));
}
static __device__ __forceinline__ void mma16816(float& c0, float& c1, float& c2, float& c3,
                                                uint32_t a0, uint32_t a1, uint32_t a2, uint32_t a3,
                                                uint32_t b0, uint32_t b1) {
    asm volatile(
        "mma.sync.aligned.m16n8k16.row.col.f32.f16.f16.f32 "
        "{%0,%1,%2,%3}, {%4,%5,%6,%7}, {%8,%9}, {%0,%1,%2,%3};"
        : "+f"(c0), "+f"(c1), "+f"(c2), "+f"(c3)
        : "r"(a0), "r"(a1), "r"(a2), "r"(a3), "r"(b0), "r"(b1));
}
static __device__ __forceinline__ void cpa16(uint32_t s, const void* g) {
    asm volatile("cp.async.cg.shared.global [%0], [%1], 16;" :: "r"(s), "l"(g));
}
static __device__ __forceinline__ void cpa_commit() {
    asm volatile("cp.async.commit_group;");
}

// ------------------------------ prep kernels --------------------------------
__global__ void prep_half(const float* __restrict__ src,
                          uint16_t* __restrict__ hi, size_t n4)
{
    uint2* h2 = reinterpret_cast<uint2*>(hi);
    for (size_t i = blockIdx.x * blockDim.x + threadIdx.x; i < n4;
         i += (size_t)gridDim.x * blockDim.x) {
        float4 v = reinterpret_cast<const float4*>(src)[i];
        __half2 h01 = __floats2half2_rn(v.x, v.y);
        __half2 h23 = __floats2half2_rn(v.z, v.w);
        uint2 hu;
        hu.x = *reinterpret_cast<uint32_t*>(&h01);
        hu.y = *reinterpret_cast<uint32_t*>(&h23);
        h2[i] = hu;
    }
}
__global__ void prep_scale_half(const float* __restrict__ U,
                                const float* __restrict__ S,
                                const float* __restrict__ eps,
                                uint16_t* __restrict__ hi, size_t n4, int rq)
{
    uint2* h2 = reinterpret_cast<uint2*>(hi);
    for (size_t i = blockIdx.x * blockDim.x + threadIdx.x; i < n4;
         i += (size_t)gridDim.x * blockDim.x) {
        size_t c4 = i % rq;
        float4 v = reinterpret_cast<const float4*>(U)[i];
        float4 sv = reinterpret_cast<const float4*>(S)[c4];
        float4 ev = reinterpret_cast<const float4*>(eps)[c4];
        v.x *= (sv.x + ev.x); v.y *= (sv.y + ev.y);
        v.z *= (sv.z + ev.z); v.w *= (sv.w + ev.w);
        __half2 h01 = __floats2half2_rn(v.x, v.y);
        __half2 h23 = __floats2half2_rn(v.z, v.w);
        uint2 hu;
        hu.x = *reinterpret_cast<uint32_t*>(&h01);
        hu.y = *reinterpret_cast<uint32_t*>(&h23);
        h2[i] = hu;
    }
}
// Vt [r][dIn] -> vh fp16 [dIn][r] (transpose)
__global__ void prep_transpose_half(const float* __restrict__ Vt,
                                    uint16_t* __restrict__ hi, int R, int dIn)
{
    __shared__ float tile[32][33];
    const int tx = threadIdx.x, ty = threadIdx.y;  // 32 x 8
    const int k0 = blockIdx.y * 32, n0 = blockIdx.x * 32;
    #pragma unroll
    for (int j = 0; j < 4; j++)
        tile[ty + j * 8][tx] = Vt[(size_t)(k0 + ty + j * 8) * dIn + n0 + tx];
    __syncthreads();
    #pragma unroll
    for (int j = 0; j < 4; j++) {
        float v = tile[tx][ty + j * 8];
        __half h = __float2half_rn(v);
        hi[(size_t)(n0 + ty + j * 8) * R + k0 + tx] = *reinterpret_cast<uint16_t*>(&h);
    }
}

// ------------------------------ GEMM core -----------------------------------
// CTA tile 128(m) x 128(n), KC=64 (128B rows, SW128). 8 warps (2m x 4n), 64x32.
// stage: A 16K | B 16K = 32KB; 3 stages = 96KB. 2 CTAs/SM.
#define KC 64
#define T_B 16384
#define STAGE 32768
#define NSTAGE 3
#define SMEM_BYTES (NSTAGE * STAGE)

template<int EPI>   // 0: fp16 output (GEMM1), 1: fp32 + bias (GEMM2)
__global__ __launch_bounds__(256, 2)
void gemm_f16(const uint16_t* __restrict__ Agh,
              const uint16_t* __restrict__ Bgh,
              float* __restrict__ Yout, const float* __restrict__ bias,
              uint16_t* __restrict__ Wh,
              int M, int N, int K)
{
    extern __shared__ char smem[];
    const uint32_t sb = smem_u32(smem);

    const int tid = threadIdx.x;
    const int wid = tid >> 5, lane = tid & 31;
    const int m0 = blockIdx.y * 128;
    const int n0 = blockIdx.x * 128;
    const int mw = (wid & 1) * 64;
    const int nw = (wid >> 1) * 32;

    const uint32_t rowA = mw + (lane & 7) + ((lane >> 3) & 1) * 8;
    const uint32_t colA = ((lane >> 4) & 1) * 16;
    const uint32_t rowB = nw + (lane & 7) + ((lane >> 4) & 1) * 8;
    const uint32_t colB = ((lane >> 3) & 1) * 16;

    float acc[4][4][4];
    #pragma unroll
    for (int i = 0; i < 4; i++)
        #pragma unroll
        for (int j = 0; j < 4; j++)
            #pragma unroll
            for (int q = 0; q < 4; q++) acc[i][j][q] = 0.f;

    const int KI = K / KC;

    // stage loader: 8 cp.async x 16B per thread (A 4, B 4)
    auto ISSUE = [&](int slot, int kt) {
        const uint32_t base = sb + (uint32_t)slot * STAGE;
        const int k0 = kt * KC;
        #pragma unroll
        for (int i = 0; i < 4; i++) {
            int c = tid + i * 256, row = c >> 3, q = c & 7;
            uint32_t off = sw128((uint32_t)(row * 128 + q * 16));
            cpa16(base + off, Agh + (size_t)(m0 + row) * K + k0 + q * 8);
        }
        #pragma unroll
        for (int i = 0; i < 4; i++) {
            int c = tid + i * 256, row = c >> 3, q = c & 7;
            uint32_t off = sw128((uint32_t)(row * 128 + q * 16));
            cpa16(base + T_B + off, Bgh + (size_t)(n0 + row) * K + k0 + q * 8);
        }
        cpa_commit();
    };

    ISSUE(0, 0);
    ISSUE(1, 1);

    // fragment double buffers
    uint32_t ah[2][4][4], bh[2][2][4];

    auto LDFRAG = [&](int buf, uint32_t stg, int kk) {
        #pragma unroll
        for (int mi = 0; mi < 4; mi++) {
            uint32_t off = sw128((rowA + mi * 16) * 128 + kk * 32 + colA);
            ldsm4(ah[buf][mi][0], ah[buf][mi][1], ah[buf][mi][2], ah[buf][mi][3],
                  stg + off);
        }
        #pragma unroll
        for (int p = 0; p < 2; p++) {
            uint32_t off = sw128((rowB + p * 16) * 128 + kk * 32 + colB);
            ldsm4(bh[buf][p][0], bh[buf][p][1], bh[buf][p][2], bh[buf][p][3],
                  stg + T_B + off);
        }
    };
    auto MMAS = [&](int buf) {
        #pragma unroll
        for (int mi = 0; mi < 4; mi++) {
            #pragma unroll
            for (int ni = 0; ni < 4; ni++) {
                float* c = acc[mi][ni];
                mma16816(c[0], c[1], c[2], c[3],
                         ah[buf][mi][0], ah[buf][mi][1], ah[buf][mi][2], ah[buf][mi][3],
                         bh[buf][ni >> 1][(ni & 1) * 2], bh[buf][ni >> 1][(ni & 1) * 2 + 1]);
            }
        }
    };

    for (int kt = 0; kt < KI; kt++) {
        asm volatile("cp.async.wait_group %0;" :: "n"(NSTAGE - 2) : "memory");
        __syncthreads();
        if (kt + NSTAGE - 1 < KI)
            ISSUE((kt + NSTAGE - 1) % NSTAGE, kt + NSTAGE - 1);

        const uint32_t stg = sb + (uint32_t)(kt % NSTAGE) * STAGE;

        LDFRAG(0, stg, 0);
        #pragma unroll
        for (int kk = 0; kk < 4; kk++) {
            if (kk < 3) LDFRAG((kk + 1) & 1, stg, kk + 1);
            MMAS(kk & 1);
        }
    }

    // ------------------------------ epilogue ---------------------------------
    const int erow = lane >> 2;
    const int ecol = (lane & 3) * 2;
    if (EPI == 1) {
        #pragma unroll
        for (int ni = 0; ni < 4; ni++) {
            int n = n0 + nw + ni * 8 + ecol;
            float2 bv = *reinterpret_cast<const float2*>(bias + n);
            #pragma unroll
            for (int mi = 0; mi < 4; mi++) {
                int m = m0 + mw + mi * 16 + erow;
                float* c = acc[mi][ni];
                *reinterpret_cast<float2*>(Yout + (size_t)m * N + n) =
                    make_float2(c[0] + bv.x, c[1] + bv.y);
                *reinterpret_cast<float2*>(Yout + (size_t)(m + 8) * N + n) =
                    make_float2(c[2] + bv.x, c[3] + bv.y);
            }
        }
    } else {
        #pragma unroll
        for (int ni = 0; ni < 4; ni++) {
            int n = n0 + nw + ni * 8 + ecol;
            #pragma unroll
            for (int mi = 0; mi < 4; mi++) {
                int m = m0 + mw + mi * 16 + erow;
                float* c = acc[mi][ni];
                #pragma unroll
                for (int half = 0; half < 2; half++) {
                    __half2 h = __floats2half2_rn(c[half * 2], c[half * 2 + 1]);
                    *reinterpret_cast<uint32_t*>(Wh + (size_t)(m + half * 8) * N + n) =
                        *reinterpret_cast<uint32_t*>(&h);
                }
            }
        }
    }
}

// =============================================================================
// Entry. Inputs: x, U, S, Vt, epsilon, bias
// =============================================================================
extern "C" void kernel_launch(void* const* d_in, const int* in_sizes, int n_in,
                              void* d_out, int out_size)
{
    const float* x    = (const float*)d_in[0];
    const float* U    = (const float*)d_in[1];
    const float* S    = (const float*)d_in[2];
    const float* Vt   = (const float*)d_in[3];
    const float* eps  = (const float*)d_in[4];
    const float* bias = (const float*)d_in[5];
    float* y = (float*)d_out;

    const int r    = in_sizes[2];          // 4096
    const int dIn  = in_sizes[3] / r;      // 4096
    const int dOut = in_sizes[1] / r;      // 4096
    const int M    = in_sizes[0] / dIn;    // 8192

    cudaFuncSetAttribute(gemm_f16<0>, cudaFuncAttributeMaxDynamicSharedMemorySize, SMEM_BYTES);
    cudaFuncSetAttribute(gemm_f16<1>, cudaFuncAttributeMaxDynamicSharedMemorySize, SMEM_BYTES);

    uint16_t *xh, *uh, *vh, *wh;
    cudaGetSymbolAddress((void**)&xh, g_xh);
    cudaGetSymbolAddress((void**)&uh, g_uh);
    cudaGetSymbolAddress((void**)&vh, g_vh);
    cudaGetSymbolAddress((void**)&wh, g_wh);

    prep_half<<<4096, 256>>>(x, xh, (size_t)M * dIn / 4);
    prep_scale_half<<<4096, 256>>>(U, S, eps, uh, (size_t)dOut * r / 4, r / 4);
    {
        dim3 grid(dIn / 32, r / 32), blk(32, 8);
        prep_transpose_half<<<grid, blk>>>(Vt, vh, r, dIn);
    }
    // GEMM1: w[dOut, dIn] = uh @ vh^T (fp16 output)
    {
        dim3 grid(dIn / 128, dOut / 128);
        gemm_f16<0><<<grid, 256, SMEM_BYTES>>>(uh, vh, nullptr, nullptr, wh,
                                               dOut, dIn, r);
    }
    // GEMM2: y[M, dOut] = xh @ wh^T + bias
    {
        dim3 grid(dOut / 128, M / 128);
        gemm_f16<1><<<grid, 256, SMEM_BYTES>>>(xh, wh, y, bias, nullptr,
                                               M, dOut, dIn);
    }
}